// round 6
// baseline (speedup 1.0000x reference)
#include <cuda_runtime.h>
#include <cuda_bf16.h>
#include <cstdint>

// ---------------------------------------------------------------------------
// NeuralODE persistent kernel, round 6:
//  - replaces the 3 blocking __syncthreads per step with 6 smem mbarriers
//    (FH1/FH2/FXB per m-tile): producer arrive right after each half-tile
//    epilogue, consumer try_wait right before the dependent GEMM. Warps drift
//    so epilogues of one warp overlap MMAs of another (lockstep broken).
//    WAR hazards proven transitively covered (see comments).
//  - per-m-tile processing (halves acc/a register arrays vs R5)
//  - ldmatrix.x4 A loads, tanh.approx.bf16x2, W2/W3 B-frags in registers
// ---------------------------------------------------------------------------

namespace {

constexpr int B_    = 4096;
constexpr int S_    = 64;
constexpr int H_    = 256;
constexpr int MROWS = 32;              // rows per CTA
constexpr int CTAS  = B_ / MROWS;      // 128
constexpr int NTH   = 256;             // 8 warps

// u32 strides (stride % 8 == 4 -> conflict-free ldmatrix phases)
constexpr int HSTR = 132;
constexpr int XSTR = 36;

// smem layout (bytes)
constexpr int SM_W1P0 = 0;                           // 16384
constexpr int SM_W1P1 = SM_W1P0 + 16384;             // 16384
constexpr int SM_W2P0 = SM_W1P1 + 16384;             // 65536 (dead after init)
constexpr int SM_W2P1 = SM_W2P0 + 65536;             // 65536 (dead after init)
constexpr int SM_W3P0 = SM_W2P1 + 65536;             // 16384 (dead after init)
constexpr int SM_W3P1 = SM_W3P0 + 16384;             // 16384 (dead after init)
constexpr int SM_H    = SM_W3P1 + 16384;             // 16896 (h1)
constexpr int SM_XB   = SM_H + MROWS * HSTR * 4;     // 4608
constexpr int SM_MB   = SM_XB + MROWS * XSTR * 4;    // 48 (6 mbarriers)
constexpr int SM_H2   = SM_W2P0;                     // h2 overlays dead W2 plane
constexpr int SMEM_BYTES = SM_MB + 64 + 192;

__device__ __forceinline__ uint32_t pack_bf16(float lo, float hi) {
    __nv_bfloat162 v = __floats2bfloat162_rn(lo, hi);
    return *reinterpret_cast<uint32_t*>(&v);
}

__device__ __forceinline__ uint32_t tanh_bf16x2(uint32_t v) {
    uint32_t r;
    asm("tanh.approx.bf16x2 %0, %1;" : "=r"(r) : "r"(v));
    return r;
}

__device__ __forceinline__ void ldsm_x4(uint32_t& r0, uint32_t& r1,
                                        uint32_t& r2, uint32_t& r3,
                                        uint32_t addr) {
    asm volatile("ldmatrix.sync.aligned.m8n8.x4.shared.b16 {%0,%1,%2,%3}, [%4];"
                 : "=r"(r0), "=r"(r1), "=r"(r2), "=r"(r3) : "r"(addr));
}

__device__ __forceinline__ void mma16816(float* d,
                                         uint32_t a0, uint32_t a1, uint32_t a2, uint32_t a3,
                                         uint32_t b0, uint32_t b1) {
    asm volatile(
        "mma.sync.aligned.m16n8k16.row.col.f32.bf16.bf16.f32 "
        "{%0,%1,%2,%3},{%4,%5,%6,%7},{%8,%9},{%0,%1,%2,%3};\n"
        : "+f"(d[0]), "+f"(d[1]), "+f"(d[2]), "+f"(d[3])
        : "r"(a0), "r"(a1), "r"(a2), "r"(a3), "r"(b0), "r"(b1));
}

// ---- mbarrier primitives (CTA scope) ----
__device__ __forceinline__ void mbar_init(uint32_t addr, uint32_t count) {
    asm volatile("mbarrier.init.shared.b64 [%0], %1;"
                 :: "r"(addr), "r"(count) : "memory");
}
__device__ __forceinline__ void mbar_arrive(uint32_t addr) {
    asm volatile("mbarrier.arrive.shared.b64 _, [%0];"
                 :: "r"(addr) : "memory");
}
__device__ __forceinline__ void mbar_wait(uint32_t addr, uint32_t parity) {
    uint32_t done;
    asm volatile(
        "{\n\t.reg .pred p;\n\t"
        "mbarrier.try_wait.parity.acquire.cta.shared::cta.b64 p, [%1], %2;\n\t"
        "selp.b32 %0, 1, 0, p;\n\t}"
        : "=r"(done) : "r"(addr), "r"(parity) : "memory");
    if (!done) {
        asm volatile(
            "{\n\t.reg .pred P1;\n\t"
            "WL_%=:\n\t"
            "mbarrier.try_wait.parity.acquire.cta.shared::cta.b64 P1, [%0], %1, 0x989680;\n\t"
            "@P1 bra.uni WD_%=;\n\t"
            "bra.uni WL_%=;\n\t"
            "WD_%=:\n\t}"
            :: "r"(addr), "r"(parity) : "memory");
    }
}

// Shuffle fp32 W[K][N] (row-major) into one bf16x2 B-fragment plane.
template <int NKB, int LOG2NKB>
__device__ void fill_plane(uint32_t* plane, const float* __restrict__ W,
                           int N, int koff, int tid) {
    const int total = N * NKB * 4;
    for (int e = tid; e < total; e += NTH) {
        int gg   = e & 7;
        int tt   = (e >> 3) & 3;
        int kbnt = e >> 5;
        int kb   = kbnt & (NKB - 1);
        int nt   = kbnt >> LOG2NKB;
        int n    = nt * 8 + gg;
        int k0   = kb * 16 + tt * 2 + koff;
        plane[e] = pack_bf16(W[k0 * N + n], W[(k0 + 1) * N + n]);
    }
}

} // namespace

extern "C" __global__ void __launch_bounds__(NTH, 1)
neuralode_persistent_kernel(const float* __restrict__ x0,
                            const float* __restrict__ W1, const float* __restrict__ b1,
                            const float* __restrict__ W2, const float* __restrict__ b2,
                            const float* __restrict__ W3, const float* __restrict__ b3,
                            const float* __restrict__ dt_scale,
                            const int*   __restrict__ num_steps,
                            float* __restrict__ out)
{
    extern __shared__ unsigned char smem_raw[];
    uint32_t* w1p0 = reinterpret_cast<uint32_t*>(smem_raw + SM_W1P0);
    uint32_t* w1p1 = reinterpret_cast<uint32_t*>(smem_raw + SM_W1P1);
    uint32_t* w2p0 = reinterpret_cast<uint32_t*>(smem_raw + SM_W2P0);
    uint32_t* w2p1 = reinterpret_cast<uint32_t*>(smem_raw + SM_W2P1);
    uint32_t* w3p0 = reinterpret_cast<uint32_t*>(smem_raw + SM_W3P0);
    uint32_t* w3p1 = reinterpret_cast<uint32_t*>(smem_raw + SM_W3P1);
    uint32_t* hbuf = reinterpret_cast<uint32_t*>(smem_raw + SM_H);
    uint32_t* h2buf= reinterpret_cast<uint32_t*>(smem_raw + SM_H2);
    uint32_t* xb   = reinterpret_cast<uint32_t*>(smem_raw + SM_XB);

    const int tid = threadIdx.x;
    const uint32_t sbase = (uint32_t)__cvta_generic_to_shared(smem_raw);

    // mbarrier addresses: FH1[2] @ +0, FH2[2] @ +16, FXB[2] @ +32
    const uint32_t mb = sbase + SM_MB;

    if (tid == 0) {
#pragma unroll
        for (int i = 0; i < 6; ++i) mbar_init(mb + i * 8, NTH);
    }

    // ---- one-time weight shuffle into fragment-ordered smem planes ----
    fill_plane<4, 2>(w1p0, W1, H_, 0, tid);
    fill_plane<4, 2>(w1p1, W1, H_, 8, tid);
    fill_plane<16, 4>(w2p0, W2, H_, 0, tid);
    fill_plane<16, 4>(w2p1, W2, H_, 8, tid);
    fill_plane<16, 4>(w3p0, W3, S_, 0, tid);
    fill_plane<16, 4>(w3p1, W3, S_, 8, tid);

    const int   nsteps  = num_steps[0];
    const float dts     = dt_scale[0] * 0.01f;
    const int   row0    = blockIdx.x * MROWS;
    const long  ostride = (long)(nsteps + 1) * S_;

    // ---- t=0: trajectory[., 0, .] = x0 ----
    for (int i = tid; i < MROWS * S_; i += NTH) {
        int r = i >> 6, c = i & 63;
        out[(long)(row0 + r) * ostride + c] = x0[(row0 + r) * S_ + c];
    }

    // ---- warp/lane decomposition: 8 warps, each 4 n-tiles x 2 m-tiles ----
    const int lane = tid & 31;
    const int g = lane >> 2, t = lane & 3;
    const int ng  = tid >> 5;          // 0..7 column group
    const int tg  = t * 8 + g;

    // ldmatrix lane-address mapping: quad q -> (row-half, k-half)
    const int q     = lane >> 3;
    const int rrow  = (lane & 7) | ((q & 1) << 3);   // 0..15
    const int koffu = (q >> 1) << 2;                 // 0 or 4 u32

    uint32_t h1a[2], h2a[2], xba[2];
#pragma unroll
    for (int mt = 0; mt < 2; ++mt) {
        h1a[mt] = sbase + SM_H  + ((mt * 16 + rrow) * HSTR + koffu) * 4;
        h2a[mt] = sbase + SM_H2 + ((mt * 16 + rrow) * HSTR + koffu) * 4;
        xba[mt] = sbase + SM_XB + ((mt * 16 + rrow) * XSTR + koffu) * 4;
    }

    __syncthreads();   // planes ready + mbarriers initialized

    // ---- register-resident weight fragments (constant over all steps) ----
    uint32_t wb2a[4][16], wb2b[4][16];
#pragma unroll
    for (int j = 0; j < 4; ++j)
#pragma unroll
        for (int kb = 0; kb < 16; ++kb) {
            int idx = ((ng * 4 + j) * 16 + kb) * 32 + tg;
            wb2a[j][kb] = w2p0[idx];
            wb2b[j][kb] = w2p1[idx];
        }
    uint32_t wb3a[16], wb3b[16];
#pragma unroll
    for (int kb = 0; kb < 16; ++kb) {
        int idx = (ng * 16 + kb) * 32 + tg;
        wb3a[kb] = w3p0[idx];
        wb3b[kb] = w3p1[idx];
    }

    // ---- register-resident biases (fragment layout) ----
    float pb1[4][2], pb2[4][2], pb3[2];
#pragma unroll
    for (int j = 0; j < 4; ++j) {
        int c = (ng * 4 + j) * 8 + t * 2;
        pb1[j][0] = b1[c];     pb1[j][1] = b1[c + 1];
        pb2[j][0] = b2[c];     pb2[j][1] = b2[c + 1];
    }
    {
        int c = ng * 8 + t * 2;
        pb3[0] = b3[c]; pb3[1] = b3[c + 1];
    }

    // ---- x state in registers (GEMM3-fragment layout, both m-tiles) ----
    float xr[2][4];
#pragma unroll
    for (int mt = 0; mt < 2; ++mt) {
        int r = mt * 16 + g;
        int colb = ng * 8 + t * 2;
        const float* p = x0 + (long)(row0 + r) * S_ + colb;
        xr[mt][0] = p[0];
        xr[mt][1] = p[1];
        xr[mt][2] = p[8 * S_];
        xr[mt][3] = p[8 * S_ + 1];
        int pidx = ng * 4 + t;
        xb[r * XSTR + pidx]       = pack_bf16(xr[mt][0], xr[mt][1]);
        xb[(r + 8) * XSTR + pidx] = pack_bf16(xr[mt][2], xr[mt][3]);
    }
    // Orders weight-plane register reads before the first h2buf overwrite, and
    // xb writes before the priming arrivals below.
    __syncthreads();

    // Prime FXB: phase 0 completes so step 0's G1 waits (parity 0) pass.
    mbar_arrive(mb + 32);      // FXB[0]
    mbar_arrive(mb + 40);      // FXB[1]

    // ======================= main time-step loop ==========================
    // Hazard notes (all transitively safe, no extra barriers needed):
    //  E1(mt,s) overwrites h1(mt): every warp at E1(mt,s) passed G3(mt,s-1)
    //    which waited FH2[mt]@(s-1); those arrivals postdate all G2 reads.
    //  E2(mt,s) overwrites h2(mt): passed G1(mt,s) waiting FXB[mt]@s whose
    //    arrivals (E3, s-1) postdate all G3 reads.
    //  E3(mt,s) overwrites xb(mt): passed G2(mt,s) waiting FH1[mt]@s whose
    //    arrivals (E1, s) postdate all G1 reads.
    for (int step = 0; step < nsteps; ++step) {
        const uint32_t par = (uint32_t)(step & 1);

        // ---- stage 1: per m-tile G1 + E1 ----
#pragma unroll
        for (int mt = 0; mt < 2; ++mt) {
            mbar_wait(mb + 32 + mt * 8, par);       // FXB[mt]

            float acc[4][4];
#pragma unroll
            for (int j = 0; j < 4; ++j)
#pragma unroll
                for (int q2 = 0; q2 < 4; ++q2) acc[j][q2] = 0.f;

#pragma unroll
            for (int kb = 0; kb < 4; ++kb) {
                uint32_t a0, a1v, a2, a3;
                ldsm_x4(a0, a1v, a2, a3, xba[mt] + kb * 32);
#pragma unroll
                for (int j = 0; j < 4; ++j) {
                    int idx = ((ng * 4 + j) * 4 + kb) * 32 + tg;
                    mma16816(acc[j], a0, a1v, a2, a3, w1p0[idx], w1p1[idx]);
                }
            }
#pragma unroll
            for (int j = 0; j < 4; ++j) {
                int pidx = (ng * 4 + j) * 4 + t;
                int r = mt * 16 + g;
                hbuf[r * HSTR + pidx] =
                    tanh_bf16x2(pack_bf16(acc[j][0] + pb1[j][0],
                                          acc[j][1] + pb1[j][1]));
                hbuf[(r + 8) * HSTR + pidx] =
                    tanh_bf16x2(pack_bf16(acc[j][2] + pb1[j][0],
                                          acc[j][3] + pb1[j][1]));
            }
            mbar_arrive(mb + mt * 8);               // FH1[mt]
        }

        // ---- stage 2: per m-tile G2 + E2 ----
#pragma unroll
        for (int mt = 0; mt < 2; ++mt) {
            mbar_wait(mb + mt * 8, par);            // FH1[mt]

            float acc[4][4];
#pragma unroll
            for (int j = 0; j < 4; ++j)
#pragma unroll
                for (int q2 = 0; q2 < 4; ++q2) acc[j][q2] = 0.f;

#pragma unroll
            for (int kb = 0; kb < 16; ++kb) {
                uint32_t a0, a1v, a2, a3;
                ldsm_x4(a0, a1v, a2, a3, h1a[mt] + kb * 32);
#pragma unroll
                for (int j = 0; j < 4; ++j)
                    mma16816(acc[j], a0, a1v, a2, a3, wb2a[j][kb], wb2b[j][kb]);
            }
#pragma unroll
            for (int j = 0; j < 4; ++j) {
                int pidx = (ng * 4 + j) * 4 + t;
                int r = mt * 16 + g;
                h2buf[r * HSTR + pidx] =
                    tanh_bf16x2(pack_bf16(acc[j][0] + pb2[j][0],
                                          acc[j][1] + pb2[j][1]));
                h2buf[(r + 8) * HSTR + pidx] =
                    tanh_bf16x2(pack_bf16(acc[j][2] + pb2[j][0],
                                          acc[j][3] + pb2[j][1]));
            }
            mbar_arrive(mb + 16 + mt * 8);          // FH2[mt]
        }

        // ---- stage 3: per m-tile G3 + E3 ----
#pragma unroll
        for (int mt = 0; mt < 2; ++mt) {
            mbar_wait(mb + 16 + mt * 8, par);       // FH2[mt]

            float acc3[4];
#pragma unroll
            for (int q2 = 0; q2 < 4; ++q2) acc3[q2] = 0.f;

#pragma unroll
            for (int kb = 0; kb < 16; ++kb) {
                uint32_t a0, a1v, a2, a3;
                ldsm_x4(a0, a1v, a2, a3, h2a[mt] + kb * 32);
                mma16816(acc3, a0, a1v, a2, a3, wb3a[kb], wb3b[kb]);
            }

            int r = mt * 16 + g;
            int colb = ng * 8 + t * 2;
            xr[mt][0] += (acc3[0] + pb3[0]) * dts;
            xr[mt][1] += (acc3[1] + pb3[1]) * dts;
            xr[mt][2] += (acc3[2] + pb3[0]) * dts;
            xr[mt][3] += (acc3[3] + pb3[1]) * dts;
            float* orow = out + (long)(row0 + r) * ostride
                        + (long)(step + 1) * S_ + colb;
            __stcs(reinterpret_cast<float2*>(orow),
                   make_float2(xr[mt][0], xr[mt][1]));
            __stcs(reinterpret_cast<float2*>(orow + 8 * ostride),
                   make_float2(xr[mt][2], xr[mt][3]));
            int pidx = ng * 4 + t;
            xb[r * XSTR + pidx]       = pack_bf16(xr[mt][0], xr[mt][1]);
            xb[(r + 8) * XSTR + pidx] = pack_bf16(xr[mt][2], xr[mt][3]);
            mbar_arrive(mb + 32 + mt * 8);          // FXB[mt] (phase step+1)
        }
    }
}

extern "C" void kernel_launch(void* const* d_in, const int* in_sizes, int n_in,
                              void* d_out, int out_size)
{
    (void)in_sizes; (void)n_in; (void)out_size;
    const float* x0       = (const float*)d_in[0];
    const float* W1       = (const float*)d_in[1];
    const float* b1       = (const float*)d_in[2];
    const float* W2       = (const float*)d_in[3];
    const float* b2       = (const float*)d_in[4];
    const float* W3       = (const float*)d_in[5];
    const float* b3       = (const float*)d_in[6];
    const float* dt_scale = (const float*)d_in[7];
    const int*   nsteps   = (const int*)d_in[8];
    float*       out      = (float*)d_out;

    cudaFuncSetAttribute(neuralode_persistent_kernel,
                         cudaFuncAttributeMaxDynamicSharedMemorySize, SMEM_BYTES);
    neuralode_persistent_kernel<<<CTAS, NTH, SMEM_BYTES>>>(
        x0, W1, b1, W2, b2, W3, b3, dt_scale, nsteps, out);
}